// round 1
// baseline (speedup 1.0000x reference)
#include <cuda_runtime.h>
#include <cstdint>
#include <cstddef>

#define D_FEAT    128
#define N_STEPS   256          // O_SIZE: only first 256 scan steps feed the output
#define N_NEURONS 1024
#define W_TILE    (D_FEAT * D_FEAT)           // 16384 floats = 64 KB per step

// smem layout (floats): Wbuf0 [0,16384) | Wbuf1 [16384,32768) | vbuf 128 | part 1024 | mbars
#define SMEM_FLOATS (2 * W_TILE + 128 + 1024 + 16)
#define SMEM_BYTES  (SMEM_FLOATS * 4)

// Scratch: u_t vectors produced by the chain, consumed by the output kernel.
__device__ __align__(16) float g_u[N_STEPS * D_FEAT];

// ---------------- PTX helpers (self-contained) ----------------
__device__ __forceinline__ unsigned smem_u32(const void* p) {
    unsigned r;
    asm("{ .reg .u64 t; cvta.to.shared.u64 t, %1; cvt.u32.u64 %0, t; }" : "=r"(r) : "l"(p));
    return r;
}
__device__ __forceinline__ void mbar_init(unsigned m, unsigned cnt) {
    asm volatile("mbarrier.init.shared.b64 [%0], %1;" :: "r"(m), "r"(cnt) : "memory");
}
__device__ __forceinline__ void mbar_expect_tx(unsigned m, unsigned bytes) {
    asm volatile("mbarrier.arrive.expect_tx.shared.b64 _, [%0], %1;" :: "r"(m), "r"(bytes) : "memory");
}
__device__ __forceinline__ void mbar_wait(unsigned m, unsigned parity) {
    asm volatile(
        "{\n\t"
        ".reg .pred P1;\n\t"
        "WL_%=:\n\t"
        "mbarrier.try_wait.parity.acquire.cta.shared::cta.b64 P1, [%0], %1, 0x989680;\n\t"
        "@P1 bra.uni WD_%=;\n\t"
        "bra.uni WL_%=;\n\t"
        "WD_%=:\n\t"
        "}"
        :: "r"(m), "r"(parity) : "memory");
}
__device__ __forceinline__ void tma_1d(unsigned dst, const void* src, unsigned bytes, unsigned m) {
    asm volatile(
        "cp.async.bulk.shared::cta.global.mbarrier::complete_tx::bytes [%0], [%1], %2, [%3];"
        :: "r"(dst), "l"(src), "r"(bytes), "r"(m) : "memory");
}
__device__ __forceinline__ float tanha(float v) {
    float r;
    asm("tanh.approx.f32 %0, %1;" : "=f"(r) : "f"(v));
    return r;
}

// ---------------- Phase A: sequential chain (single CTA) ----------------
// v_0[j] = (pos_head[0]·dsum) * xsum[j]
// u_t    = v_t @ W[t]          (128x128 f32 matvec)
// v_{t+1}= tanh(a[t, t+1] * u_t)
// Stores all u_t to g_u. W double-buffered via 1-D bulk TMA.
__global__ void __launch_bounds__(256, 1) chain_kernel(
    const float* __restrict__ x,         // (256,128)
    const float* __restrict__ pos_head,  // (1024,64) — only row 0 used
    const float* __restrict__ pos_tail,  // (1024,64) — only rows [0,256) used
    const float* __restrict__ W,         // (768,128,128) — only [0,256) used
    const float* __restrict__ a)         // (768,1024)
{
    extern __shared__ float sm[];
    float* Wbuf0 = sm;
    float* Wbuf1 = sm + W_TILE;
    float* vbuf  = sm + 2 * W_TILE;   // 128 floats
    float* part  = vbuf + 128;        // 1024 floats (also setup scratch)
    unsigned mb0 = smem_u32(part + 1024);
    unsigned mb1 = mb0 + 8;

    const int tid  = threadIdx.x;
    const int w    = tid >> 5;
    const int lane = tid & 31;

    // ---- setup: compute v_0 (fused, tiny) ----
    {
        // xsum partials: thread (h=tid>>7, j=tid&127) sums 128 rows of column j
        const int jcol = tid & 127, h = tid >> 7;
        float s = 0.f;
        const float* xp = x + (size_t)(h * 128) * D_FEAT + jcol;
        #pragma unroll 8
        for (int i = 0; i < 128; i++) s += xp[(size_t)i * D_FEAT];
        part[tid] = s;
        __syncthreads();

        // dsum partials: thread (q=tid>>6, d=tid&63) sums 64 rows of pos_tail column d
        const int d = tid & 63, q = tid >> 6;
        float sd = 0.f;
        const float* pp = pos_tail + (size_t)(q * 64) * 64 + d;
        #pragma unroll 8
        for (int r = 0; r < 64; r++) sd += pp[r * 64];
        part[256 + tid] = sd;
        __syncthreads();

        if (tid < 64) {
            float dv = part[256 + tid] + part[320 + tid] + part[384 + tid] + part[448 + tid];
            part[512 + tid] = dv * pos_head[tid];   // pos_head row 0
        }
        __syncthreads();
        if (tid == 0) {
            float s0 = 0.f;
            #pragma unroll
            for (int dd = 0; dd < 64; dd++) s0 += part[512 + dd];
            part[576] = s0;
        }
        __syncthreads();
        if (tid < 128) vbuf[tid] = part[576] * (part[tid] + part[128 + tid]);
    }

    if (tid == 0) { mbar_init(mb0, 1); mbar_init(mb1, 1); }
    __syncthreads();   // publishes v_0 and mbarrier init

    if (tid == 0) {
        mbar_expect_tx(mb0, W_TILE * 4);
        tma_1d(smem_u32(Wbuf0), W, W_TILE * 4, mb0);
        mbar_expect_tx(mb1, W_TILE * 4);
        tma_1d(smem_u32(Wbuf1), W + W_TILE, W_TILE * 4, mb1);
    }

    for (int t = 0; t < N_STEPS; t++) {
        const float* Wb = (t & 1) ? Wbuf1 : Wbuf0;
        const unsigned mb = (t & 1) ? mb1 : mb0;
        const unsigned parity = (t >> 1) & 1;

        // Warm L2 for step t+6 (keeps TMA completion off the DRAM latency path).
        {
            const int tp = t + 6;
            if (tp < N_STEPS) {
                const float* pf = W + (size_t)tp * W_TILE + tid * 64;
                asm volatile("prefetch.global.L2 [%0];" :: "l"(pf));
                asm volatile("prefetch.global.L2 [%0];" :: "l"(pf + 32));
            }
        }

        mbar_wait(mb, parity);

        // Partial matvec: warp w covers rows j = w, w+8, ..., w+120; lane owns k-chunk [4*lane, 4*lane+4)
        float4 acc = make_float4(0.f, 0.f, 0.f, 0.f);
        const float4* W4 = (const float4*)Wb;
        #pragma unroll
        for (int r = 0; r < 16; r++) {
            const int j = (r << 3) + w;
            const float vj = vbuf[j];                 // warp-uniform broadcast
            const float4 wv = W4[j * 32 + lane];      // conflict-free LDS.128
            acc.x += vj * wv.x; acc.y += vj * wv.y;
            acc.z += vj * wv.z; acc.w += vj * wv.w;
        }
        ((float4*)part)[w * 32 + lane] = acc;         // part[w*128 + k]
        __syncthreads();

        if (tid < 128) {   // thread k reduces 8 warp partials
            float u = part[tid]       + part[128 + tid] + part[256 + tid] + part[384 + tid]
                    + part[512 + tid] + part[640 + tid] + part[768 + tid] + part[896 + tid];
            g_u[t * 128 + tid] = u;
            if (t < N_STEPS - 1) {
                const float c = __ldg(a + (size_t)t * N_NEURONS + (t + 1));
                vbuf[tid] = tanhf(c * u);   // accurate tanh: errors here feed forward
            }
        }
        __syncthreads();

        if (tid == 0 && t + 2 < N_STEPS) {   // buffer (t&1) is free now
            mbar_expect_tx(mb, W_TILE * 4);
            tma_1d(smem_u32((t & 1) ? Wbuf1 : Wbuf0), W + (size_t)(t + 2) * W_TILE, W_TILE * 4, mb);
        }
    }
}

// ---------------- Phase B: output generation (full chip, DRAM-write bound) ----------------
// out[t, l, j] = tanh(a[t, l] * u_t[j]);  grid = 256 t-values x 8 l-blocks of 128 rows.
__global__ void __launch_bounds__(256) out_kernel(const float* __restrict__ a,
                                                  float* __restrict__ out)
{
    __shared__ float4 us[32];
    const int t  = blockIdx.x >> 3;
    const int lb = blockIdx.x & 7;

    if (threadIdx.x < 32) us[threadIdx.x] = ((const float4*)g_u)[t * 32 + threadIdx.x];
    __syncthreads();

    const int w = threadIdx.x >> 5, lane = threadIdx.x & 31;
    const float4 u4 = us[lane];                       // lane's 4 j-columns, reused 16x
    const float* arow = a + (size_t)t * N_NEURONS + lb * 128;
    float4* op = (float4*)out + ((size_t)t * N_NEURONS + (size_t)lb * 128) * 32 + lane;

    #pragma unroll
    for (int it = 0; it < 16; it++) {
        const int l = (it << 3) + w;
        const float av = __ldg(arow + l);             // warp-uniform
        float4 r;
        r.x = tanha(av * u4.x);
        r.y = tanha(av * u4.y);
        r.z = tanha(av * u4.z);
        r.w = tanha(av * u4.w);
        __stcs(op + (size_t)l * 32, r);               // streaming store, 512B/warp coalesced
    }
}

// ---------------- launch ----------------
extern "C" void kernel_launch(void* const* d_in, const int* in_sizes, int n_in,
                              void* d_out, int out_size) {
    const float* x  = (const float*)d_in[0];
    const float* ph = (const float*)d_in[1];
    const float* pt = (const float*)d_in[2];
    const float* W  = (const float*)d_in[3];
    const float* a  = (const float*)d_in[4];

    cudaFuncSetAttribute(chain_kernel, cudaFuncAttributeMaxDynamicSharedMemorySize, SMEM_BYTES);
    chain_kernel<<<1, 256, SMEM_BYTES>>>(x, ph, pt, W, a);
    out_kernel<<<N_STEPS * 8, 256>>>(a, (float*)d_out);
}